// round 8
// baseline (speedup 1.0000x reference)
#include <cuda_runtime.h>
#include <cstdint>

#define N_NODES 50000
#define N_EDGES 800000
#define F_X 128
#define F_E 128
#define HIDDEN 512
#define F_OUT 128

// ---------------- scratch (static device globals; no runtime alloc) --------
__device__ float    g_agg[(size_t)N_NODES * F_E];              // 25.6 MB fp32
__device__ uint32_t g_A[(size_t)N_NODES * (F_E + F_X)];        // 51.2 MB tf32 [50000][256]
__device__ uint32_t g_h[(size_t)N_NODES * HIDDEN];             // 102.4 MB tf32 bits
__device__ uint32_t g_W1t[(size_t)HIDDEN * (F_E + F_X)];       // W1^T tf32 [512][256]
__device__ uint32_t g_W2t[(size_t)F_OUT * HIDDEN];             // W2^T tf32 [128][512]

__device__ __forceinline__ uint32_t f2tf32(float f) {
    uint32_t r; asm("cvt.rna.tf32.f32 %0, %1;" : "=r"(r) : "f"(f)); return r;
}
__device__ __forceinline__ uint32_t smem_u32(const void* p) {
    uint32_t a;
    asm("{ .reg .u64 t; cvta.to.shared.u64 t, %1; cvt.u32.u64 %0, t; }"
        : "=r"(a) : "l"(p));
    return a;
}

// ---------------------------------------------------------------------------
// launch #1: zero agg buffer
// ---------------------------------------------------------------------------
__global__ void zero_agg_kernel() {
    int i = blockIdx.x * blockDim.x + threadIdx.x;
    const int n4 = N_NODES * F_E / 4;
    float4* p = reinterpret_cast<float4*>(g_agg);
    if (i < n4) p[i] = make_float4(0.f, 0.f, 0.f, 0.f);
}

// ---------------------------------------------------------------------------
// launch #2: scatter-add, one warp per edge, red.global.add.v4.f32
// ---------------------------------------------------------------------------
__global__ void __launch_bounds__(256) scatter_edges_kernel(
    const float4* __restrict__ edge_attr, const int* __restrict__ receivers)
{
    int gt = blockIdx.x * blockDim.x + threadIdx.x;
    int edge = gt >> 5;
    int lane = gt & 31;
    if (edge >= N_EDGES) return;

    int r = __ldg(receivers + edge);
    float4 v = edge_attr[(size_t)edge * 32 + lane];
    float* dst = g_agg + (size_t)r * F_E + lane * 4;
    asm volatile("red.global.add.v4.f32 [%0], {%1,%2,%3,%4};"
                 :: "l"(dst), "f"(v.x), "f"(v.y), "f"(v.z), "f"(v.w)
                 : "memory");
}

// ---------------------------------------------------------------------------
// launch #3: fused prep — concat(g_agg|nodes)->g_A tf32, W1->W1t, W2->W2t
// item space: [0, NC) concat float4 | [NC, NC+NW1) W1t | [.., +NW2) W2t
// ---------------------------------------------------------------------------
#define PREP_NC  (N_NODES * 64)                  // 3,200,000 float4 items
#define PREP_NW1 (HIDDEN * (F_E + F_X))          // 131,072
#define PREP_NW2 (F_OUT * HIDDEN)                // 65,536
#define PREP_TOTAL (PREP_NC + PREP_NW1 + PREP_NW2)

__global__ void __launch_bounds__(256) prep_kernel(
    const float4* __restrict__ nodes,
    const float* __restrict__ W1, const float* __restrict__ W2)
{
    int i = blockIdx.x * blockDim.x + threadIdx.x;
    if (i < PREP_NC) {
        int row = i >> 6, c4 = i & 63;
        float4 v = (c4 < 32)
            ? reinterpret_cast<const float4*>(g_agg)[(size_t)row * 32 + c4]
            : nodes[(size_t)row * 32 + (c4 - 32)];
        uint4 t;
        t.x = f2tf32(v.x); t.y = f2tf32(v.y);
        t.z = f2tf32(v.z); t.w = f2tf32(v.w);
        reinterpret_cast<uint4*>(g_A)[i] = t;
    } else if (i < PREP_NC + PREP_NW1) {
        int idx = i - PREP_NC;
        int n = idx >> 8, k = idx & 255;                 // K=256
        g_W1t[idx] = f2tf32(W1[(size_t)k * HIDDEN + n]);
    } else if (i < PREP_TOTAL) {
        int idx = i - PREP_NC - PREP_NW1;
        int n = idx >> 9, k = idx & 511;                 // K=512
        g_W2t[idx] = f2tf32(W2[(size_t)k * F_OUT + n]);
    }
}

// ---------------------------------------------------------------------------
// launches #4/#5: cp.async 4-stage pipelined tf32 mma GEMM (unchanged, 291us)
// BM=128, BN=128, BK=16; 256 threads = 8 warps (2m x 4n), warp 64x32.
// ---------------------------------------------------------------------------
#define STAGE_WORDS (2 * 128 * 20)          // 5120

template <bool L1>
__global__ void __launch_bounds__(256)
gemm_pipe_kernel(const uint32_t* __restrict__ Aglob,
                 const uint32_t* __restrict__ Wt,
                 const float* __restrict__ bias,
                 float* __restrict__ Cout)
{
    constexpr int K = L1 ? (F_E + F_X) : HIDDEN;
    constexpr int N = L1 ? HIDDEN : F_OUT;
    constexpr int M = N_NODES;
    constexpr int NT = K / 16;

    extern __shared__ uint32_t smem[];
    const uint32_t sbase = smem_u32(smem);

    const int tid  = threadIdx.x;
    const int lane = tid & 31;
    const int warp = tid >> 5;
    const int m0 = blockIdx.y * 128;
    const int n0 = blockIdx.x * 128;
    const int warp_m = (warp >> 2) * 64;
    const int warp_n = (warp & 3) * 32;
    const int g  = lane >> 2;
    const int t4 = lane & 3;

    const int row0 = tid >> 2,         q0 = tid & 3;
    const int row1 = (tid + 256) >> 2, q1 = tid & 3;

    const int a_ok0 = (m0 + row0) < M ? 16 : 0;
    const int a_ok1 = (m0 + row1) < M ? 16 : 0;

    float acc[4][4][4];
    #pragma unroll
    for (int mt = 0; mt < 4; ++mt)
        #pragma unroll
        for (int nt = 0; nt < 4; ++nt)
            #pragma unroll
            for (int i = 0; i < 4; ++i) acc[mt][nt][i] = 0.f;

    auto issue = [&](int tile, int slot) {
        const int k0 = tile * 16;
        uint32_t ab = sbase + (slot * STAGE_WORDS) * 4;
        uint32_t bb = ab + 2560 * 4;
        asm volatile("cp.async.cg.shared.global [%0], [%1], 16, %2;"
            :: "r"(ab + (row0 * 20 + q0 * 4) * 4),
               "l"(Aglob + (size_t)(m0 + row0) * K + k0 + q0 * 4),
               "r"(a_ok0) : "memory");
        asm volatile("cp.async.cg.shared.global [%0], [%1], 16, %2;"
            :: "r"(ab + (row1 * 20 + q1 * 4) * 4),
               "l"(Aglob + (size_t)(m0 + row1) * K + k0 + q1 * 4),
               "r"(a_ok1) : "memory");
        asm volatile("cp.async.cg.shared.global [%0], [%1], 16;"
            :: "r"(bb + (row0 * 20 + q0 * 4) * 4),
               "l"(Wt + (size_t)(n0 + row0) * K + k0 + q0 * 4) : "memory");
        asm volatile("cp.async.cg.shared.global [%0], [%1], 16;"
            :: "r"(bb + (row1 * 20 + q1 * 4) * 4),
               "l"(Wt + (size_t)(n0 + row1) * K + k0 + q1 * 4) : "memory");
    };

    issue(0, 0); asm volatile("cp.async.commit_group;" ::: "memory");
    issue(1, 1); asm volatile("cp.async.commit_group;" ::: "memory");
    issue(2, 2); asm volatile("cp.async.commit_group;" ::: "memory");

    for (int it = 0; it < NT; ++it) {
        asm volatile("cp.async.wait_group 2;" ::: "memory");
        __syncthreads();

        const uint32_t* As = smem + (it & 3) * STAGE_WORDS;
        const uint32_t* Bs = As + 2560;

        #pragma unroll
        for (int ks = 0; ks < 2; ++ks) {
            const int kb = ks * 8;
            uint32_t a[4][4], b[4][2];
            #pragma unroll
            for (int mt = 0; mt < 4; ++mt) {
                int mb = warp_m + mt * 16;
                a[mt][0] = As[(mb + g)     * 20 + kb + t4];
                a[mt][1] = As[(mb + g + 8) * 20 + kb + t4];
                a[mt][2] = As[(mb + g)     * 20 + kb + t4 + 4];
                a[mt][3] = As[(mb + g + 8) * 20 + kb + t4 + 4];
            }
            #pragma unroll
            for (int nt = 0; nt < 4; ++nt) {
                int nb = warp_n + nt * 8;
                b[nt][0] = Bs[(nb + g) * 20 + kb + t4];
                b[nt][1] = Bs[(nb + g) * 20 + kb + t4 + 4];
            }
            #pragma unroll
            for (int mt = 0; mt < 4; ++mt)
                #pragma unroll
                for (int nt = 0; nt < 4; ++nt)
                    asm volatile(
                        "mma.sync.aligned.m16n8k8.row.col.f32.tf32.tf32.f32 "
                        "{%0,%1,%2,%3}, {%4,%5,%6,%7}, {%8,%9}, {%0,%1,%2,%3};"
                        : "+f"(acc[mt][nt][0]), "+f"(acc[mt][nt][1]),
                          "+f"(acc[mt][nt][2]), "+f"(acc[mt][nt][3])
                        : "r"(a[mt][0]), "r"(a[mt][1]),
                          "r"(a[mt][2]), "r"(a[mt][3]),
                          "r"(b[nt][0]), "r"(b[nt][1]));
        }
        __syncthreads();

        if (it + 3 < NT) issue(it + 3, (it + 3) & 3);
        asm volatile("cp.async.commit_group;" ::: "memory");
    }

    #pragma unroll
    for (int mt = 0; mt < 4; ++mt) {
        #pragma unroll
        for (int nt = 0; nt < 4; ++nt) {
            int gc = n0 + warp_n + nt * 8 + t4 * 2;
            float2 bv = *reinterpret_cast<const float2*>(bias + gc);
            #pragma unroll
            for (int hh = 0; hh < 2; ++hh) {
                int gr = m0 + warp_m + mt * 16 + g + hh * 8;
                if (gr >= M) continue;
                float ox = acc[mt][nt][hh * 2 + 0] + bv.x;
                float oy = acc[mt][nt][hh * 2 + 1] + bv.y;
                if (L1) {
                    uint2 t;
                    t.x = f2tf32(fmaxf(ox, 0.f));
                    t.y = f2tf32(fmaxf(oy, 0.f));
                    *reinterpret_cast<uint2*>(g_h + (size_t)gr * N + gc) = t;
                } else {
                    float2 o = make_float2(ox, oy);
                    *reinterpret_cast<float2*>(Cout + (size_t)gr * N + gc) = o;
                }
            }
        }
    }
}

// ---------------------------------------------------------------------------
// launch order: zero(1) -> scatter(2) -> prep(3) -> gemm1(4) -> gemm2(5)
// (#4 is what ncu captures -> gemm1 profile next round)
// Inputs: nodes, edge_attr, senders, receivers, W1, b1, W2, b2
// ---------------------------------------------------------------------------
extern "C" void kernel_launch(void* const* d_in, const int* in_sizes, int n_in,
                              void* d_out, int out_size)
{
    const float*  nodes     = (const float*)d_in[0];
    const float4* edge_attr = (const float4*)d_in[1];
    const int*    receivers = (const int*)d_in[3];
    const float*  W1        = (const float*)d_in[4];
    const float*  b1        = (const float*)d_in[5];
    const float*  W2        = (const float*)d_in[6];
    const float*  b2        = (const float*)d_in[7];
    float* out = (float*)d_out;

    uint32_t *w1t = nullptr, *w2t = nullptr, *gA = nullptr, *gh = nullptr;
    cudaGetSymbolAddress((void**)&w1t, g_W1t);
    cudaGetSymbolAddress((void**)&w2t, g_W2t);
    cudaGetSymbolAddress((void**)&gA,  g_A);
    cudaGetSymbolAddress((void**)&gh,  g_h);

    static bool attr_set = false;
    if (!attr_set) {
        cudaFuncSetAttribute(gemm_pipe_kernel<true>,
                             cudaFuncAttributeMaxDynamicSharedMemorySize,
                             4 * STAGE_WORDS * 4);
        cudaFuncSetAttribute(gemm_pipe_kernel<false>,
                             cudaFuncAttributeMaxDynamicSharedMemorySize,
                             4 * STAGE_WORDS * 4);
        attr_set = true;
    }

    // 1
    zero_agg_kernel<<<(N_NODES * F_E / 4 + 255) / 256, 256>>>();
    // 2
    {
        long long total = (long long)N_EDGES * 32;
        int blocks = (int)((total + 255) / 256);
        scatter_edges_kernel<<<blocks, 256>>>(edge_attr, receivers);
    }
    // 3
    prep_kernel<<<(PREP_TOTAL + 255) / 256, 256>>>(
        (const float4*)nodes, W1, W2);
    // 4
    {
        dim3 grid(HIDDEN / 128, (N_NODES + 127) / 128);   // (4, 391)
        gemm_pipe_kernel<true><<<grid, 256, 4 * STAGE_WORDS * 4>>>(
            gA, w1t, b1, nullptr);
    }
    // 5
    {
        dim3 grid(F_OUT / 128, (N_NODES + 127) / 128);    // (1, 391)
        gemm_pipe_kernel<false><<<grid, 256, 4 * STAGE_WORDS * 4>>>(
            gh, w2t, b2, out);
    }
}

// round 10
// speedup vs baseline: 1.6331x; 1.6331x over previous
#include <cuda_runtime.h>
#include <cstdint>

#define N_NODES 50000
#define N_EDGES 800000
#define F_X 128
#define F_E 128
#define HIDDEN 512
#define F_OUT 128

// ---------------- scratch (static device globals; no runtime alloc) --------
__device__ float    g_agg[(size_t)N_NODES * F_E];              // 25.6 MB fp32
__device__ uint32_t g_A[(size_t)N_NODES * (F_E + F_X)];        // 51.2 MB tf32 [50000][256]
__device__ uint32_t g_h[(size_t)N_NODES * HIDDEN];             // 102.4 MB tf32 bits
__device__ uint32_t g_W1t[(size_t)HIDDEN * (F_E + F_X)];       // W1^T tf32 [512][256]
__device__ uint32_t g_W2t[(size_t)F_OUT * HIDDEN];             // W2^T tf32 [128][512]

__device__ __forceinline__ uint32_t f2tf32(float f) {
    uint32_t r; asm("cvt.rna.tf32.f32 %0, %1;" : "=r"(r) : "f"(f)); return r;
}
__device__ __forceinline__ uint32_t smem_u32(const void* p) {
    uint32_t a;
    asm("{ .reg .u64 t; cvta.to.shared.u64 t, %1; cvt.u32.u64 %0, t; }"
        : "=r"(a) : "l"(p));
    return a;
}

// ---------------------------------------------------------------------------
// launch #1: zero agg buffer
// ---------------------------------------------------------------------------
__global__ void zero_agg_kernel() {
    int i = blockIdx.x * blockDim.x + threadIdx.x;
    const int n4 = N_NODES * F_E / 4;
    float4* p = reinterpret_cast<float4*>(g_agg);
    if (i < n4) p[i] = make_float4(0.f, 0.f, 0.f, 0.f);
}

// ---------------------------------------------------------------------------
// launch #2: scatter-add, one warp per edge, red.global.add.v4.f32
// ---------------------------------------------------------------------------
__global__ void __launch_bounds__(256) scatter_edges_kernel(
    const float4* __restrict__ edge_attr, const int* __restrict__ receivers)
{
    int gt = blockIdx.x * blockDim.x + threadIdx.x;
    int edge = gt >> 5;
    int lane = gt & 31;
    if (edge >= N_EDGES) return;

    int r = __ldg(receivers + edge);
    float4 v = edge_attr[(size_t)edge * 32 + lane];
    float* dst = g_agg + (size_t)r * F_E + lane * 4;
    asm volatile("red.global.add.v4.f32 [%0], {%1,%2,%3,%4};"
                 :: "l"(dst), "f"(v.x), "f"(v.y), "f"(v.z), "f"(v.w)
                 : "memory");
}

// ---------------------------------------------------------------------------
// launch #3: fused prep — concat(g_agg|nodes)->g_A tf32, W1->W1t, W2->W2t
// ---------------------------------------------------------------------------
#define PREP_NC  (N_NODES * 64)                  // 3,200,000 float4 items
#define PREP_NW1 (HIDDEN * (F_E + F_X))          // 131,072
#define PREP_NW2 (F_OUT * HIDDEN)                // 65,536
#define PREP_TOTAL (PREP_NC + PREP_NW1 + PREP_NW2)

__global__ void __launch_bounds__(256) prep_kernel(
    const float4* __restrict__ nodes,
    const float* __restrict__ W1, const float* __restrict__ W2)
{
    int i = blockIdx.x * blockDim.x + threadIdx.x;
    if (i < PREP_NC) {
        int row = i >> 6, c4 = i & 63;
        float4 v = (c4 < 32)
            ? reinterpret_cast<const float4*>(g_agg)[(size_t)row * 32 + c4]
            : nodes[(size_t)row * 32 + (c4 - 32)];
        uint4 t;
        t.x = f2tf32(v.x); t.y = f2tf32(v.y);
        t.z = f2tf32(v.z); t.w = f2tf32(v.w);
        reinterpret_cast<uint4*>(g_A)[i] = t;
    } else if (i < PREP_NC + PREP_NW1) {
        int idx = i - PREP_NC;
        int n = idx >> 8, k = idx & 255;                 // K=256
        g_W1t[idx] = f2tf32(W1[(size_t)k * HIDDEN + n]);
    } else if (i < PREP_TOTAL) {
        int idx = i - PREP_NC - PREP_NW1;
        int n = idx >> 9, k = idx & 511;                 // K=512
        g_W2t[idx] = f2tf32(W2[(size_t)k * F_OUT + n]);
    }
}

// ---------------------------------------------------------------------------
// launches #4/#5: cp.async 3-stage pipelined tf32 mma GEMM, BK=32.
// BM=128, BN=128; 256 threads = 8 warps (2m x 4n), warp 64x32.
// Stage: A 128x36 + B 128x36 words (stride 36 -> frag bank = 4g+t4 = lane,
// conflict-free).  3 stages = 108 KB dynamic smem, 2 CTAs/SM.
// ---------------------------------------------------------------------------
#define STAGE_WORDS (2 * 128 * 36)          // 9216 words = 36 KB

template <bool L1>
__global__ void __launch_bounds__(256)
gemm_pipe_kernel(const uint32_t* __restrict__ Aglob,
                 const uint32_t* __restrict__ Wt,
                 const float* __restrict__ bias,
                 float* __restrict__ Cout)
{
    constexpr int K = L1 ? (F_E + F_X) : HIDDEN;
    constexpr int N = L1 ? HIDDEN : F_OUT;
    constexpr int M = N_NODES;
    constexpr int NT = K / 32;

    extern __shared__ uint32_t smem[];
    const uint32_t sbase = smem_u32(smem);

    const int tid  = threadIdx.x;
    const int lane = tid & 31;
    const int warp = tid >> 5;
    const int m0 = blockIdx.y * 128;
    const int n0 = blockIdx.x * 128;
    const int warp_m = (warp >> 2) * 64;
    const int warp_n = (warp & 3) * 32;
    const int g  = lane >> 2;
    const int t4 = lane & 3;

    // staging: 128 rows x 32 k = 1024 float4 per operand; 4 chunks/thread
    int srow[4], sq[4], a_ok[4];
    #pragma unroll
    for (int i = 0; i < 4; ++i) {
        int e = tid + i * 256;
        srow[i] = e >> 3;
        sq[i]   = (e & 7) * 4;
        a_ok[i] = (m0 + srow[i]) < M ? 16 : 0;
    }

    float acc[4][4][4];
    #pragma unroll
    for (int mt = 0; mt < 4; ++mt)
        #pragma unroll
        for (int nt = 0; nt < 4; ++nt)
            #pragma unroll
            for (int i = 0; i < 4; ++i) acc[mt][nt][i] = 0.f;

    auto issue = [&](int tile, int slot) {
        const int k0 = tile * 32;
        uint32_t ab = sbase + (slot * STAGE_WORDS) * 4;
        uint32_t bb = ab + (128 * 36) * 4;
        #pragma unroll
        for (int i = 0; i < 4; ++i) {
            asm volatile("cp.async.cg.shared.global [%0], [%1], 16, %2;"
                :: "r"(ab + (srow[i] * 36 + sq[i]) * 4),
                   "l"(Aglob + (size_t)(m0 + srow[i]) * K + k0 + sq[i]),
                   "r"(a_ok[i]) : "memory");
        }
        #pragma unroll
        for (int i = 0; i < 4; ++i) {
            asm volatile("cp.async.cg.shared.global [%0], [%1], 16;"
                :: "r"(bb + (srow[i] * 36 + sq[i]) * 4),
                   "l"(Wt + (size_t)(n0 + srow[i]) * K + k0 + sq[i])
                : "memory");
        }
    };

    issue(0, 0); asm volatile("cp.async.commit_group;" ::: "memory");
    issue(1, 1); asm volatile("cp.async.commit_group;" ::: "memory");

    for (int it = 0; it < NT; ++it) {
        asm volatile("cp.async.wait_group 1;" ::: "memory");
        __syncthreads();

        const uint32_t* As = smem + (it % 3) * STAGE_WORDS;
        const uint32_t* Bs = As + 128 * 36;

        #pragma unroll
        for (int ks = 0; ks < 4; ++ks) {
            const int kb = ks * 8;
            uint32_t a[4][4], b[4][2];
            #pragma unroll
            for (int mt = 0; mt < 4; ++mt) {
                int mb = warp_m + mt * 16;
                a[mt][0] = As[(mb + g)     * 36 + kb + t4];
                a[mt][1] = As[(mb + g + 8) * 36 + kb + t4];
                a[mt][2] = As[(mb + g)     * 36 + kb + t4 + 4];
                a[mt][3] = As[(mb + g + 8) * 36 + kb + t4 + 4];
            }
            #pragma unroll
            for (int nt = 0; nt < 4; ++nt) {
                int nb = warp_n + nt * 8;
                b[nt][0] = Bs[(nb + g) * 36 + kb + t4];
                b[nt][1] = Bs[(nb + g) * 36 + kb + t4 + 4];
            }
            #pragma unroll
            for (int mt = 0; mt < 4; ++mt)
                #pragma unroll
                for (int nt = 0; nt < 4; ++nt)
                    asm volatile(
                        "mma.sync.aligned.m16n8k8.row.col.f32.tf32.tf32.f32 "
                        "{%0,%1,%2,%3}, {%4,%5,%6,%7}, {%8,%9}, {%0,%1,%2,%3};"
                        : "+f"(acc[mt][nt][0]), "+f"(acc[mt][nt][1]),
                          "+f"(acc[mt][nt][2]), "+f"(acc[mt][nt][3])
                        : "r"(a[mt][0]), "r"(a[mt][1]),
                          "r"(a[mt][2]), "r"(a[mt][3]),
                          "r"(b[nt][0]), "r"(b[nt][1]));
        }
        __syncthreads();

        if (it + 2 < NT) issue(it + 2, (it + 2) % 3);
        asm volatile("cp.async.commit_group;" ::: "memory");   // keep count exact
    }

    // ---- epilogue ----
    #pragma unroll
    for (int mt = 0; mt < 4; ++mt) {
        #pragma unroll
        for (int nt = 0; nt < 4; ++nt) {
            int gc = n0 + warp_n + nt * 8 + t4 * 2;
            float2 bv = *reinterpret_cast<const float2*>(bias + gc);
            #pragma unroll
            for (int hh = 0; hh < 2; ++hh) {
                int gr = m0 + warp_m + mt * 16 + g + hh * 8;
                if (gr >= M) continue;
                float ox = acc[mt][nt][hh * 2 + 0] + bv.x;
                float oy = acc[mt][nt][hh * 2 + 1] + bv.y;
                if (L1) {
                    uint2 t;
                    t.x = f2tf32(fmaxf(ox, 0.f));
                    t.y = f2tf32(fmaxf(oy, 0.f));
                    *reinterpret_cast<uint2*>(g_h + (size_t)gr * N + gc) = t;
                } else {
                    float2 o = make_float2(ox, oy);
                    *reinterpret_cast<float2*>(Cout + (size_t)gr * N + gc) = o;
                }
            }
        }
    }
}

// ---------------------------------------------------------------------------
// launch order: zero(1) -> scatter(2) -> prep(3) -> gemm1(4) -> gemm2(5)
// (#4 is what ncu captures -> gemm1 profile)
// Inputs: nodes, edge_attr, senders, receivers, W1, b1, W2, b2
// ---------------------------------------------------------------------------
extern "C" void kernel_launch(void* const* d_in, const int* in_sizes, int n_in,
                              void* d_out, int out_size)
{
    const float*  nodes     = (const float*)d_in[0];
    const float4* edge_attr = (const float4*)d_in[1];
    const int*    receivers = (const int*)d_in[3];
    const float*  W1        = (const float*)d_in[4];
    const float*  b1        = (const float*)d_in[5];
    const float*  W2        = (const float*)d_in[6];
    const float*  b2        = (const float*)d_in[7];
    float* out = (float*)d_out;

    uint32_t *w1t = nullptr, *w2t = nullptr, *gA = nullptr, *gh = nullptr;
    cudaGetSymbolAddress((void**)&w1t, g_W1t);
    cudaGetSymbolAddress((void**)&w2t, g_W2t);
    cudaGetSymbolAddress((void**)&gA,  g_A);
    cudaGetSymbolAddress((void**)&gh,  g_h);

    static bool attr_set = false;
    if (!attr_set) {
        cudaFuncSetAttribute(gemm_pipe_kernel<true>,
                             cudaFuncAttributeMaxDynamicSharedMemorySize,
                             3 * STAGE_WORDS * 4);
        cudaFuncSetAttribute(gemm_pipe_kernel<false>,
                             cudaFuncAttributeMaxDynamicSharedMemorySize,
                             3 * STAGE_WORDS * 4);
        attr_set = true;
    }

    // 1
    zero_agg_kernel<<<(N_NODES * F_E / 4 + 255) / 256, 256>>>();
    // 2
    {
        long long total = (long long)N_EDGES * 32;
        int blocks = (int)((total + 255) / 256);
        scatter_edges_kernel<<<blocks, 256>>>(edge_attr, receivers);
    }
    // 3
    prep_kernel<<<(PREP_TOTAL + 255) / 256, 256>>>(
        (const float4*)nodes, W1, W2);
    // 4
    {
        dim3 grid(HIDDEN / 128, (N_NODES + 127) / 128);   // (4, 391)
        gemm_pipe_kernel<true><<<grid, 256, 3 * STAGE_WORDS * 4>>>(
            gA, w1t, b1, nullptr);
    }
    // 5
    {
        dim3 grid(F_OUT / 128, (N_NODES + 127) / 128);    // (1, 391)
        gemm_pipe_kernel<false><<<grid, 256, 3 * STAGE_WORDS * 4>>>(
            gh, w2t, b2, out);
    }
}